// round 15
// baseline (speedup 1.0000x reference)
#include <cuda_runtime.h>
#include <cuda_fp16.h>
#include <math.h>
#include <stdint.h>

#define B_  32
#define L_  1024
#define D_  1024
#define H_  16
#define DV_ 64
#define M_  (B_ * L_)

// ---- scratch (static device arrays; no allocation allowed) ----
__device__ float g_q[B_ * D_];
__device__ float g_u[B_ * H_ * D_];
__device__ float g_c[B_ * H_];
__device__ float g_attn[B_ * H_ * L_];
__device__ __align__(16) __half g_Bh[D_ * D_];         // wv^T fp16 [n][k]
__device__ __align__(16) __half g_Ax[(size_t)M_ * D_]; // enc fp16 [m][k]

__device__ __forceinline__ float rate_of(int l) {
    return (float)(L_ - l - 1) * (1.0f / (float)L_) + 1.0f;
}

__device__ __forceinline__ uint32_t smem_u32(const void* p) {
    uint32_t a;
    asm("{ .reg .u64 t; cvta.to.shared.u64 t, %1; cvt.u32.u64 %0, t; }"
        : "=r"(a) : "l"(p));
    return a;
}

__device__ __forceinline__ uint32_t pack_h(__half a, __half b) {
    return (uint32_t)__half_as_ushort(a) | ((uint32_t)__half_as_ushort(b) << 16);
}

// ===========================================================================
// Kernel 0a: enc -> fp16 (row-major unchanged)
// ===========================================================================
__global__ void k_conv_enc(const float* __restrict__ enc) {
    size_t i = (size_t)blockIdx.x * 256 + threadIdx.x;   // float4 index
    float4 v = reinterpret_cast<const float4*>(enc)[i];
    reinterpret_cast<uint2*>(g_Ax)[i] =
        make_uint2(pack_h(__float2half(v.x), __float2half(v.y)),
                   pack_h(__float2half(v.z), __float2half(v.w)));
}

// ===========================================================================
// Kernel 0b: transpose + fp16 convert wv:  g_Bh[n][k] = fp16(wv[k][n])
// ===========================================================================
__global__ void k_conv_wv(const float* __restrict__ wv) {
    __shared__ float tile[32][33];
    int bx = blockIdx.x, by = blockIdx.y;
    int tx = threadIdx.x, ty = threadIdx.y;   // 32 x 8
#pragma unroll
    for (int j = 0; j < 4; j++)
        tile[ty + 8 * j][tx] = wv[(size_t)(by * 32 + ty + 8 * j) * D_ + bx * 32 + tx];
    __syncthreads();
#pragma unroll
    for (int j = 0; j < 4; j++) {
        float x = tile[tx][ty + 8 * j];
        size_t o = (size_t)(bx * 32 + ty + 8 * j) * D_ + by * 32 + tx;
        g_Bh[o] = __float2half(x);
    }
}

// ===========================================================================
// Kernel 1: q[b,:] = enc[b, L-1, :] @ wq + bq
// ===========================================================================
__global__ void k_q(const float* __restrict__ enc, const float* __restrict__ wq,
                    const float* __restrict__ bq) {
    __shared__ float sE[D_];
    int b = blockIdx.y;
    const float* row = enc + ((size_t)b * L_ + (L_ - 1)) * D_;
    for (int i = threadIdx.x; i < D_; i += blockDim.x) sE[i] = row[i];
    __syncthreads();
    int j = blockIdx.x * blockDim.x + threadIdx.x;
    float s0 = 0.f, s1 = 0.f, s2 = 0.f, s3 = 0.f;
#pragma unroll 2
    for (int d = 0; d < D_; d += 4) {
        s0 += sE[d + 0] * wq[(size_t)(d + 0) * D_ + j];
        s1 += sE[d + 1] * wq[(size_t)(d + 1) * D_ + j];
        s2 += sE[d + 2] * wq[(size_t)(d + 2) * D_ + j];
        s3 += sE[d + 3] * wq[(size_t)(d + 3) * D_ + j];
    }
    g_q[b * D_ + j] = (s0 + s1) + (s2 + s3) + bq[j];
}

// ===========================================================================
// Kernel 2 (v2): wk read exactly ONCE.  grid (8 d-chunks, 16 heads) x 128.
//   thread owns d = bx*128+tid: w[64] in regs; loops 32 batches from smem q.
// ===========================================================================
__global__ void __launch_bounds__(128) k_u(const float* __restrict__ wk,
                                           const float* __restrict__ bk) {
    __shared__ float sq[32 * 64];
    __shared__ float sbk[64];
    int h = blockIdx.y, d0 = blockIdx.x * 128, tid = threadIdx.x;
    for (int i = tid; i < 512; i += 128) {
        int b = i >> 4, dv4 = i & 15;
        reinterpret_cast<float4*>(sq)[i] =
            *reinterpret_cast<const float4*>(g_q + b * D_ + h * DV_ + dv4 * 4);
    }
    if (tid < 16)
        reinterpret_cast<float4*>(sbk)[tid] =
            *reinterpret_cast<const float4*>(bk + h * DV_ + tid * 4);
    __syncthreads();

    int d = d0 + tid;
    float w[64];
    const float4* wr = reinterpret_cast<const float4*>(wk + (size_t)d * D_ + h * DV_);
#pragma unroll
    for (int i = 0; i < 16; i++) {
        float4 t = wr[i];
        w[4 * i + 0] = t.x; w[4 * i + 1] = t.y; w[4 * i + 2] = t.z; w[4 * i + 3] = t.w;
    }
#pragma unroll 4
    for (int b = 0; b < 32; b++) {
        const float4* q4 = reinterpret_cast<const float4*>(sq + b * 64);
        float s = 0.f;
#pragma unroll
        for (int k4 = 0; k4 < 16; k4++) {
            float4 q = q4[k4];
            s += w[4 * k4 + 0] * q.x + w[4 * k4 + 1] * q.y +
                 w[4 * k4 + 2] * q.z + w[4 * k4 + 3] * q.w;
        }
        g_u[(size_t)(b * H_ + h) * D_ + d] = s;
    }
    if (blockIdx.x == 0 && tid < 32) {
        float c = 0.f;
#pragma unroll
        for (int k = 0; k < 64; k++) c += sq[tid * 64 + k] * sbk[k];
        g_c[tid * H_ + h] = c;
    }
}

// ===========================================================================
// Kernel 3 (v4): 512 thr, warp = 1 head (u = 32 regs), enc tile in smem.
// ===========================================================================
#define SC_ROWS 16
__global__ void __launch_bounds__(512, 2) k_scores(const float* __restrict__ enc) {
    extern __shared__ float sE[];             // SC_ROWS x 1024 = 64KB
    int b = blockIdx.y, l0 = blockIdx.x * SC_ROWS;
    const float4* base =
        reinterpret_cast<const float4*>(enc + ((size_t)b * L_ + l0) * D_);
    for (int i = threadIdx.x; i < SC_ROWS * D_ / 4; i += 512)
        reinterpret_cast<float4*>(sE)[i] = base[i];

    int wid = threadIdx.x >> 5, lane = threadIdx.x & 31;   // wid = head
    const float4* up =
        reinterpret_cast<const float4*>(g_u + (size_t)(b * H_ + wid) * D_);
    float4 u[8];
#pragma unroll
    for (int i = 0; i < 8; i++) u[i] = up[i * 32 + lane];
    float c = g_c[b * H_ + wid];
    float inv_t = 1.0f / (sqrtf((float)D_) + 1e-5f);
    __syncthreads();

#pragma unroll 1
    for (int r = 0; r < SC_ROWS; r++) {
        const float4* er = reinterpret_cast<const float4*>(&sE[r * D_]);
        float a = 0.f;
#pragma unroll
        for (int i = 0; i < 8; i++) {
            float4 e = er[i * 32 + lane];
            a += e.x * u[i].x + e.y * u[i].y + e.z * u[i].z + e.w * u[i].w;
        }
#pragma unroll
        for (int off = 16; off; off >>= 1)
            a += __shfl_xor_sync(0xFFFFFFFFu, a, off);
        if (lane == 0) {
            int l = l0 + r;
            g_attn[(size_t)(b * H_ + wid) * L_ + l] = rate_of(l) * ((a + c) * inv_t);
        }
    }
}

// ===========================================================================
// Kernel 3b: in-place log-softmax over l per (b,h)
// ===========================================================================
__global__ void k_lsm() {
    int bh = blockIdx.x;
    float* x = g_attn + (size_t)bh * L_;
    __shared__ float red[256];
    int t = threadIdx.x;
    float v0 = x[t], v1 = x[t + 256], v2 = x[t + 512], v3 = x[t + 768];
    float m = fmaxf(fmaxf(v0, v1), fmaxf(v2, v3));
    red[t] = m; __syncthreads();
    for (int s = 128; s; s >>= 1) { if (t < s) red[t] = fmaxf(red[t], red[t + s]); __syncthreads(); }
    m = red[0]; __syncthreads();
    float e = expf(v0 - m) + expf(v1 - m) + expf(v2 - m) + expf(v3 - m);
    red[t] = e; __syncthreads();
    for (int s = 128; s; s >>= 1) { if (t < s) red[t] += red[t + s]; __syncthreads(); }
    float lse = m + logf(red[0]);
    x[t] = v0 - lse; x[t + 256] = v1 - lse; x[t + 512] = v2 - lse; x[t + 768] = v3 - lse;
}

// ===========================================================================
// Kernel 4: fp16 GEMM, both operands via cp.async + fused epilogue
//   acc = A*B (fp32 accum); BM=128, BN=256, BK=32; 8 warps, warp 64x64.
// ===========================================================================
#define OFF_A  0
#define OFF_B  8192
#define STG_SZ 24576
#define SMEM_GEMM (2 * STG_SZ)
#define NT_ (D_ / 32)

__device__ __forceinline__ uint32_t swz(int row, int kb) {
    int chunk = kb >> 3;
    return (uint32_t)(row * 64 + ((chunk ^ ((row >> 1) & 3)) << 4));
}

__device__ __forceinline__ void ldsm4(uint32_t r[4], uint32_t addr) {
    asm volatile("ldmatrix.sync.aligned.m8n8.x4.shared.b16 {%0,%1,%2,%3}, [%4];"
                 : "=r"(r[0]), "=r"(r[1]), "=r"(r[2]), "=r"(r[3]) : "r"(addr));
}

__device__ __forceinline__ void mma_f16(float c[4], const uint32_t a[4],
                                        const uint32_t b[2]) {
    asm("mma.sync.aligned.m16n8k16.row.col.f32.f16.f16.f32 "
        "{%0,%1,%2,%3}, {%4,%5,%6,%7}, {%8,%9}, {%0,%1,%2,%3};"
        : "+f"(c[0]), "+f"(c[1]), "+f"(c[2]), "+f"(c[3])
        : "r"(a[0]), "r"(a[1]), "r"(a[2]), "r"(a[3]), "r"(b[0]), "r"(b[1]));
}

__device__ __forceinline__ void cp16(uint32_t dst, const void* src) {
    asm volatile("cp.async.cg.shared.global [%0], [%1], 16;" :: "r"(dst), "l"(src));
}
__device__ __forceinline__ void cp_commit() {
    asm volatile("cp.async.commit_group;" ::: "memory");
}
__device__ __forceinline__ void cp_wait0() {
    asm volatile("cp.async.wait_group 0;" ::: "memory");
}

// A: 128 rows x 32 k fp16 = 8KB -> 512 cp16, 2 per thread
__device__ __forceinline__ void cpasync_A(uint32_t stg, int cRow, int kt, int tid) {
#pragma unroll
    for (int i = 0; i < 2; i++) {
        int idx = tid + 256 * i;
        int r = idx >> 2, kc4 = idx & 3;
        size_t off = (size_t)(cRow * 128 + r) * D_ + kt * 32 + kc4 * 8;
        cp16(stg + OFF_A + swz(r, kc4 * 8), g_Ax + off);
    }
}

// B: 256 rows x 32 k fp16 = 16KB -> 1024 cp16, 4 per thread
__device__ __forceinline__ void cpasync_B(uint32_t stg, int cCol, int kt, int tid) {
#pragma unroll
    for (int i = 0; i < 4; i++) {
        int idx = tid + 256 * i;
        int n = idx >> 2, kc4 = idx & 3;
        size_t off = (size_t)(cCol * 256 + n) * D_ + kt * 32 + kc4 * 8;
        cp16(stg + OFF_B + swz(n, kc4 * 8), g_Bh + off);
    }
}

__global__ void __launch_bounds__(256, 1) k_gemm_mma(
    const float* __restrict__ enc,
    const float* __restrict__ bv,
    float* __restrict__ out)
{
    extern __shared__ char smem[];
    const uint32_t sbase = smem_u32(smem);
    const int tid = threadIdx.x;
    const int wid = tid >> 5, lane = tid & 31;
    const int wm = (wid & 1) * 64;
    const int wn = (wid >> 1) * 64;
    const int cCol = blockIdx.x, cRow = blockIdx.y;
    const int lr = lane & 7, grp = lane >> 3;

    float acc[4][8][4];
#pragma unroll
    for (int f = 0; f < 4; f++)
#pragma unroll
        for (int g = 0; g < 8; g++)
#pragma unroll
            for (int j = 0; j < 4; j++) acc[f][g][j] = 0.f;

    cpasync_A(sbase, cRow, 0, tid);
    cpasync_B(sbase, cCol, 0, tid);
    cp_commit();
    cp_wait0();
    __syncthreads();

    for (int t = 0; t < NT_; t++) {
        if (t + 1 < NT_) {
            uint32_t s1 = sbase + ((t + 1) & 1) * STG_SZ;
            cpasync_A(s1, cRow, t + 1, tid);
            cpasync_B(s1, cCol, t + 1, tid);
            cp_commit();
        }
        const uint32_t stg = sbase + (t & 1) * STG_SZ;
#pragma unroll
        for (int kk = 0; kk < 2; kk++) {
            uint32_t ah[4][4];
#pragma unroll
            for (int f = 0; f < 4; f++) {
                int row = wm + f * 16 + (grp & 1) * 8 + lr;
                int kb = kk * 16 + (grp >> 1) * 8;
                ldsm4(ah[f], stg + OFF_A + swz(row, kb));
            }
            uint32_t bh[8][2];
#pragma unroll
            for (int gp = 0; gp < 4; gp++) {
                int n = wn + (gp * 2 + (grp >> 1)) * 8 + lr;
                int kb = kk * 16 + (grp & 1) * 8;
                uint32_t tr[4];
                ldsm4(tr, stg + OFF_B + swz(n, kb));
                bh[gp * 2][0] = tr[0]; bh[gp * 2][1] = tr[1];
                bh[gp * 2 + 1][0] = tr[2]; bh[gp * 2 + 1][1] = tr[3];
            }
#pragma unroll
            for (int f = 0; f < 4; f++)
#pragma unroll
                for (int g = 0; g < 8; g++)
                    mma_f16(acc[f][g], ah[f], bh[g]);
        }
        if (t + 1 < NT_) {
            cp_wait0();
            __syncthreads();
        }
    }

    // ---- fused epilogue
    const int qr = lane >> 2, qc = lane & 3;
#pragma unroll
    for (int f = 0; f < 4; f++) {
#pragma unroll
        for (int half = 0; half < 2; half++) {
            int row = cRow * 128 + wm + f * 16 + half * 8 + qr;
            int b = row >> 10, l = row & (L_ - 1);
            float rt = rate_of(l);
            const float* attn_row = g_attn + (size_t)b * H_ * L_ + l;
            const float* encrow = enc + (size_t)row * D_;
            float* outrow = out + (size_t)row * D_;
#pragma unroll
            for (int g = 0; g < 8; g++) {
                int col = cCol * 256 + wn + g * 8 + qc * 2;
                int h = col >> 6;
                float a = attn_row[(size_t)h * L_] * rt;
                float2 bvv = *reinterpret_cast<const float2*>(bv + col);
                float2 rv  = *reinterpret_cast<const float2*>(encrow + col);
                float2 o;
                o.x = (acc[f][g][half * 2 + 0] + bvv.x) * a + rv.x;
                o.y = (acc[f][g][half * 2 + 1] + bvv.y) * a + rv.y;
                *reinterpret_cast<float2*>(outrow + col) = o;
            }
        }
    }
}

// ===========================================================================
// Kernel 5: row LayerNorm in place (shfl + single cross-warp reduce)
// ===========================================================================
__global__ void k_ln(float* __restrict__ out,
                     const float* __restrict__ gamma,
                     const float* __restrict__ beta)
{
    size_t row = blockIdx.x;
    float4* o4 = reinterpret_cast<float4*>(out + row * D_);
    int t = threadIdx.x;
    float4 v = o4[t];
    float s  = v.x + v.y + v.z + v.w;
    float ss = v.x * v.x + v.y * v.y + v.z * v.z + v.w * v.w;
#pragma unroll
    for (int off = 16; off; off >>= 1) {
        s  += __shfl_xor_sync(0xFFFFFFFFu, s, off);
        ss += __shfl_xor_sync(0xFFFFFFFFu, ss, off);
    }
    __shared__ float as_[8], ass_[8];
    if ((t & 31) == 0) { as_[t >> 5] = s; ass_[t >> 5] = ss; }
    __syncthreads();
    float S = 0.f, SS = 0.f;
#pragma unroll
    for (int i = 0; i < 8; i++) { S += as_[i]; SS += ass_[i]; }
    float mean = S * (1.0f / (float)D_);
    float var  = SS * (1.0f / (float)D_) - mean * mean;
    float inv  = rsqrtf(var + 1e-5f);
    const float4* g4 = reinterpret_cast<const float4*>(gamma);
    const float4* b4 = reinterpret_cast<const float4*>(beta);
    float4 g = g4[t], bb = b4[t];
    float4 r;
    r.x = (v.x - mean) * inv * g.x + bb.x;
    r.y = (v.y - mean) * inv * g.y + bb.y;
    r.z = (v.z - mean) * inv * g.z + bb.z;
    r.w = (v.w - mean) * inv * g.w + bb.w;
    o4[t] = r;
}

// ===========================================================================
extern "C" void kernel_launch(void* const* d_in, const int* in_sizes, int n_in,
                              void* d_out, int out_size) {
    const float* enc   = (const float*)d_in[0];
    const float* wq    = (const float*)d_in[1];
    const float* bq    = (const float*)d_in[2];
    const float* wk    = (const float*)d_in[3];
    const float* bk    = (const float*)d_in[4];
    const float* wv    = (const float*)d_in[5];
    const float* bv    = (const float*)d_in[6];
    const float* gamma = (const float*)d_in[7];
    const float* beta  = (const float*)d_in[8];
    float* out = (float*)d_out;

    cudaFuncSetAttribute(k_gemm_mma, cudaFuncAttributeMaxDynamicSharedMemorySize,
                         SMEM_GEMM);
    cudaFuncSetAttribute(k_scores, cudaFuncAttributeMaxDynamicSharedMemorySize,
                         SC_ROWS * D_ * 4);

    k_conv_enc<<<M_ * (D_ / 4) / 256, 256>>>(enc);
    k_conv_wv<<<dim3(D_ / 32, D_ / 32), dim3(32, 8)>>>(wv);
    k_q<<<dim3(D_ / 256, B_), 256>>>(enc, wq, bq);
    k_u<<<dim3(8, H_), 128>>>(wk, bk);
    k_scores<<<dim3(L_ / SC_ROWS, B_), 512, SC_ROWS * D_ * 4>>>(enc);
    k_lsm<<<B_ * H_, 256>>>();
    k_gemm_mma<<<dim3(D_ / 256, M_ / 128), 256, SMEM_GEMM>>>(enc, bv, out);
    k_ln<<<M_, 256>>>(out, gamma, beta);
}

// round 17
// speedup vs baseline: 1.1812x; 1.1812x over previous
#include <cuda_runtime.h>
#include <cuda_fp16.h>
#include <math.h>
#include <stdint.h>

#define B_  32
#define L_  1024
#define D_  1024
#define H_  16
#define DV_ 64
#define M_  (B_ * L_)

// ---- scratch (static device arrays; no allocation allowed) ----
__device__ float g_q[B_ * D_];
__device__ float g_u[B_ * H_ * D_];
__device__ float g_c[B_ * H_];
__device__ float g_attn[B_ * H_ * L_];
__device__ __align__(16) __half g_Bh[D_ * D_];   // wv^T fp16 [n][k]

__device__ __forceinline__ float rate_of(int l) {
    return (float)(L_ - l - 1) * (1.0f / (float)L_) + 1.0f;
}

__device__ __forceinline__ uint32_t smem_u32(const void* p) {
    uint32_t a;
    asm("{ .reg .u64 t; cvta.to.shared.u64 t, %1; cvt.u32.u64 %0, t; }"
        : "=r"(a) : "l"(p));
    return a;
}

__device__ __forceinline__ uint32_t pack_h(__half a, __half b) {
    return (uint32_t)__half_as_ushort(a) | ((uint32_t)__half_as_ushort(b) << 16);
}

// ===========================================================================
// Kernel 0: transpose + fp16 convert wv:  g_Bh[n][k] = fp16(wv[k][n])
// ===========================================================================
__global__ void k_conv_wv(const float* __restrict__ wv) {
    __shared__ float tile[32][33];
    int bx = blockIdx.x, by = blockIdx.y;
    int tx = threadIdx.x, ty = threadIdx.y;   // 32 x 8
#pragma unroll
    for (int j = 0; j < 4; j++)
        tile[ty + 8 * j][tx] = wv[(size_t)(by * 32 + ty + 8 * j) * D_ + bx * 32 + tx];
    __syncthreads();
#pragma unroll
    for (int j = 0; j < 4; j++) {
        float x = tile[tx][ty + 8 * j];
        size_t o = (size_t)(bx * 32 + ty + 8 * j) * D_ + by * 32 + tx;
        g_Bh[o] = __float2half(x);
    }
}

// ===========================================================================
// Kernel 1: q[b,:] = enc[b, L-1, :] @ wq + bq
// ===========================================================================
__global__ void k_q(const float* __restrict__ enc, const float* __restrict__ wq,
                    const float* __restrict__ bq) {
    __shared__ float sE[D_];
    int b = blockIdx.y;
    const float* row = enc + ((size_t)b * L_ + (L_ - 1)) * D_;
    for (int i = threadIdx.x; i < D_; i += blockDim.x) sE[i] = row[i];
    __syncthreads();
    int j = blockIdx.x * blockDim.x + threadIdx.x;
    float s0 = 0.f, s1 = 0.f, s2 = 0.f, s3 = 0.f;
#pragma unroll 2
    for (int d = 0; d < D_; d += 4) {
        s0 += sE[d + 0] * wq[(size_t)(d + 0) * D_ + j];
        s1 += sE[d + 1] * wq[(size_t)(d + 1) * D_ + j];
        s2 += sE[d + 2] * wq[(size_t)(d + 2) * D_ + j];
        s3 += sE[d + 3] * wq[(size_t)(d + 3) * D_ + j];
    }
    g_q[b * D_ + j] = (s0 + s1) + (s2 + s3) + bq[j];
}

// ===========================================================================
// Kernel 2 (v2, proven): wk read exactly once. grid (8, 16) x 128.
// ===========================================================================
__global__ void __launch_bounds__(128) k_u(const float* __restrict__ wk,
                                           const float* __restrict__ bk) {
    __shared__ float sq[32 * 64];
    __shared__ float sbk[64];
    int h = blockIdx.y, d0 = blockIdx.x * 128, tid = threadIdx.x;
    for (int i = tid; i < 512; i += 128) {
        int b = i >> 4, dv4 = i & 15;
        reinterpret_cast<float4*>(sq)[i] =
            *reinterpret_cast<const float4*>(g_q + b * D_ + h * DV_ + dv4 * 4);
    }
    if (tid < 16)
        reinterpret_cast<float4*>(sbk)[tid] =
            *reinterpret_cast<const float4*>(bk + h * DV_ + tid * 4);
    __syncthreads();

    int d = d0 + tid;
    float w[64];
    const float4* wr = reinterpret_cast<const float4*>(wk + (size_t)d * D_ + h * DV_);
#pragma unroll
    for (int i = 0; i < 16; i++) {
        float4 t = wr[i];
        w[4 * i + 0] = t.x; w[4 * i + 1] = t.y; w[4 * i + 2] = t.z; w[4 * i + 3] = t.w;
    }
#pragma unroll 4
    for (int b = 0; b < 32; b++) {
        const float4* q4 = reinterpret_cast<const float4*>(sq + b * 64);
        float s = 0.f;
#pragma unroll
        for (int k4 = 0; k4 < 16; k4++) {
            float4 q = q4[k4];
            s += w[4 * k4 + 0] * q.x + w[4 * k4 + 1] * q.y +
                 w[4 * k4 + 2] * q.z + w[4 * k4 + 3] * q.w;
        }
        g_u[(size_t)(b * H_ + h) * D_ + d] = s;
    }
    if (blockIdx.x == 0 && tid < 32) {
        float c = 0.f;
#pragma unroll
        for (int k = 0; k < 64; k++) c += sq[tid * 64 + k] * sbk[k];
        g_c[tid * H_ + h] = c;
    }
}

// ===========================================================================
// Kernel 3 (v2, known 109us): u in registers (2 heads/warp), enc in smem.
// ===========================================================================
#define SC_ROWS 16
__global__ void __launch_bounds__(256) k_scores(const float* __restrict__ enc) {
    extern __shared__ float sE[];             // SC_ROWS x 1024 = 64KB
    int b = blockIdx.y, l0 = blockIdx.x * SC_ROWS;
    const float4* base =
        reinterpret_cast<const float4*>(enc + ((size_t)b * L_ + l0) * D_);
    for (int i = threadIdx.x; i < SC_ROWS * D_ / 4; i += 256)
        reinterpret_cast<float4*>(sE)[i] = base[i];

    int wid = threadIdx.x >> 5, lane = threadIdx.x & 31;
    int h0 = wid * 2, h1 = wid * 2 + 1;
    const float* up0 = g_u + (size_t)(b * H_ + h0) * D_;
    const float* up1 = g_u + (size_t)(b * H_ + h1) * D_;
    float4 u0[8], u1[8];
#pragma unroll
    for (int i = 0; i < 8; i++) {
        u0[i] = *reinterpret_cast<const float4*>(up0 + i * 128 + lane * 4);
        u1[i] = *reinterpret_cast<const float4*>(up1 + i * 128 + lane * 4);
    }
    float c0 = g_c[b * H_ + h0], c1 = g_c[b * H_ + h1];
    float inv_t = 1.0f / (sqrtf((float)D_) + 1e-5f);
    __syncthreads();

#pragma unroll 1
    for (int r = 0; r < SC_ROWS; r++) {
        float a0 = 0.f, a1 = 0.f;
#pragma unroll
        for (int i = 0; i < 8; i++) {
            float4 e = *reinterpret_cast<const float4*>(&sE[r * D_ + i * 128 + lane * 4]);
            a0 += e.x * u0[i].x + e.y * u0[i].y + e.z * u0[i].z + e.w * u0[i].w;
            a1 += e.x * u1[i].x + e.y * u1[i].y + e.z * u1[i].z + e.w * u1[i].w;
        }
#pragma unroll
        for (int off = 16; off; off >>= 1) {
            a0 += __shfl_xor_sync(0xFFFFFFFFu, a0, off);
            a1 += __shfl_xor_sync(0xFFFFFFFFu, a1, off);
        }
        if (lane == 0) {
            int l = l0 + r;
            float rt = rate_of(l);
            g_attn[(size_t)(b * H_ + h0) * L_ + l] = rt * ((a0 + c0) * inv_t);
            g_attn[(size_t)(b * H_ + h1) * L_ + l] = rt * ((a1 + c1) * inv_t);
        }
    }
}

// ===========================================================================
// Kernel 3b: in-place log-softmax over l per (b,h)
// ===========================================================================
__global__ void k_lsm() {
    int bh = blockIdx.x;
    float* x = g_attn + (size_t)bh * L_;
    __shared__ float red[256];
    int t = threadIdx.x;
    float v0 = x[t], v1 = x[t + 256], v2 = x[t + 512], v3 = x[t + 768];
    float m = fmaxf(fmaxf(v0, v1), fmaxf(v2, v3));
    red[t] = m; __syncthreads();
    for (int s = 128; s; s >>= 1) { if (t < s) red[t] = fmaxf(red[t], red[t + s]); __syncthreads(); }
    m = red[0]; __syncthreads();
    float e = expf(v0 - m) + expf(v1 - m) + expf(v2 - m) + expf(v3 - m);
    red[t] = e; __syncthreads();
    for (int s = 128; s; s >>= 1) { if (t < s) red[t] += red[t + s]; __syncthreads(); }
    float lse = m + logf(red[0]);
    x[t] = v0 - lse; x[t + 256] = v1 - lse; x[t + 512] = v2 - lse; x[t + 768] = v3 - lse;
}

// ===========================================================================
// Kernel 4: fp16 GEMM, 512 threads / 16 warps (2m x 8n), warp tile 64x32.
//   BM=128, BN=256, BK=32; inline A convert (proven free); B via cp.async.
// ===========================================================================
#define OFF_A  0
#define OFF_B  8192
#define STG_SZ 24576
#define SMEM_GEMM (2 * STG_SZ)
#define NT_ (D_ / 32)

__device__ __forceinline__ uint32_t swz(int row, int kb) {
    int chunk = kb >> 3;
    return (uint32_t)(row * 64 + ((chunk ^ ((row >> 1) & 3)) << 4));
}

__device__ __forceinline__ void ldsm4(uint32_t r[4], uint32_t addr) {
    asm volatile("ldmatrix.sync.aligned.m8n8.x4.shared.b16 {%0,%1,%2,%3}, [%4];"
                 : "=r"(r[0]), "=r"(r[1]), "=r"(r[2]), "=r"(r[3]) : "r"(addr));
}

__device__ __forceinline__ void mma_f16(float c[4], const uint32_t a[4],
                                        const uint32_t b[2]) {
    asm("mma.sync.aligned.m16n8k16.row.col.f32.f16.f16.f32 "
        "{%0,%1,%2,%3}, {%4,%5,%6,%7}, {%8,%9}, {%0,%1,%2,%3};"
        : "+f"(c[0]), "+f"(c[1]), "+f"(c[2]), "+f"(c[3])
        : "r"(a[0]), "r"(a[1]), "r"(a[2]), "r"(a[3]), "r"(b[0]), "r"(b[1]));
}

__device__ __forceinline__ void cp16(uint32_t dst, const void* src) {
    asm volatile("cp.async.cg.shared.global [%0], [%1], 16;" :: "r"(dst), "l"(src));
}
__device__ __forceinline__ void cp_commit() {
    asm volatile("cp.async.commit_group;" ::: "memory");
}
__device__ __forceinline__ void cp_wait0() {
    asm volatile("cp.async.wait_group 0;" ::: "memory");
}

// A: 128 rows x 32 k fp32 -> 1024 float4, 2 per thread (512 thr)
__device__ __forceinline__ void ldg_A(const float* __restrict__ enc,
                                      int cRow, int kt, int tid, float4 aR[2]) {
#pragma unroll
    for (int i = 0; i < 2; i++) {
        int idx = tid + 512 * i;
        int r = idx >> 3, kc = (idx & 7) * 4;
        aR[i] = *reinterpret_cast<const float4*>(
            enc + (size_t)(cRow * 128 + r) * D_ + kt * 32 + kc);
    }
}

__device__ __forceinline__ void sts_A(char* st, int tid, const float4 aR[2]) {
#pragma unroll
    for (int i = 0; i < 2; i++) {
        int idx = tid + 512 * i;
        int r = idx >> 3, kc = (idx & 7) * 4;
        float4 v = aR[i];
        uint32_t a = swz(r, kc & ~7) + (kc & 7) * 2;
        *reinterpret_cast<uint2*>(st + OFF_A + a) =
            make_uint2(pack_h(__float2half(v.x), __float2half(v.y)),
                       pack_h(__float2half(v.z), __float2half(v.w)));
    }
}

// B: 256 rows x 32 k fp16 -> 1024 cp16, 2 per thread (512 thr)
__device__ __forceinline__ void cpasync_B(uint32_t stg, int cCol, int kt, int tid) {
#pragma unroll
    for (int i = 0; i < 2; i++) {
        int idx = tid + 512 * i;
        int n = idx >> 2, kc4 = idx & 3;
        size_t off = (size_t)(cCol * 256 + n) * D_ + kt * 32 + kc4 * 8;
        cp16(stg + OFF_B + swz(n, kc4 * 8), g_Bh + off);
    }
}

__global__ void __launch_bounds__(512, 1) k_gemm_mma(
    const float* __restrict__ enc,
    const float* __restrict__ bv,
    float* __restrict__ out)
{
    extern __shared__ char smem[];
    const uint32_t sbase = smem_u32(smem);
    const int tid = threadIdx.x;
    const int wid = tid >> 5, lane = tid & 31;
    const int wm = (wid & 1) * 64;        // 2 warps in m
    const int wn = (wid >> 1) * 32;       // 8 warps in n
    const int cCol = blockIdx.x, cRow = blockIdx.y;
    const int lr = lane & 7, grp = lane >> 3;

    float acc[4][4][4];
#pragma unroll
    for (int f = 0; f < 4; f++)
#pragma unroll
        for (int g = 0; g < 4; g++)
#pragma unroll
            for (int j = 0; j < 4; j++) acc[f][g][j] = 0.f;

    float4 aR[2];
    ldg_A(enc, cRow, 0, tid, aR);
    cpasync_B(sbase, cCol, 0, tid);
    cp_commit();
    sts_A(smem, tid, aR);
    cp_wait0();
    __syncthreads();

    for (int t = 0; t < NT_; t++) {
        if (t + 1 < NT_) {
            ldg_A(enc, cRow, t + 1, tid, aR);
            cpasync_B(sbase + ((t + 1) & 1) * STG_SZ, cCol, t + 1, tid);
            cp_commit();
        }
        const uint32_t stg = sbase + (t & 1) * STG_SZ;
#pragma unroll
        for (int kk = 0; kk < 2; kk++) {
            uint32_t ah[4][4];
#pragma unroll
            for (int f = 0; f < 4; f++) {
                int row = wm + f * 16 + (grp & 1) * 8 + lr;
                int kb = kk * 16 + (grp >> 1) * 8;
                ldsm4(ah[f], stg + OFF_A + swz(row, kb));
            }
            uint32_t bh[4][2];
#pragma unroll
            for (int gp = 0; gp < 2; gp++) {
                int n = wn + (gp * 2 + (grp >> 1)) * 8 + lr;
                int kb = kk * 16 + (grp & 1) * 8;
                uint32_t tr[4];
                ldsm4(tr, stg + OFF_B + swz(n, kb));
                bh[gp * 2][0] = tr[0]; bh[gp * 2][1] = tr[1];
                bh[gp * 2 + 1][0] = tr[2]; bh[gp * 2 + 1][1] = tr[3];
            }
#pragma unroll
            for (int f = 0; f < 4; f++)
#pragma unroll
                for (int g = 0; g < 4; g++)
                    mma_f16(acc[f][g], ah[f], bh[g]);
        }
        if (t + 1 < NT_) {
            sts_A(smem + ((t + 1) & 1) * STG_SZ, tid, aR);
            cp_wait0();
            __syncthreads();
        }
    }

    // ---- fused epilogue
    const int qr = lane >> 2, qc = lane & 3;
#pragma unroll
    for (int f = 0; f < 4; f++) {
#pragma unroll
        for (int half = 0; half < 2; half++) {
            int row = cRow * 128 + wm + f * 16 + half * 8 + qr;
            int b = row >> 10, l = row & (L_ - 1);
            float rt = rate_of(l);
            const float* attn_row = g_attn + (size_t)b * H_ * L_ + l;
            const float* encrow = enc + (size_t)row * D_;
            float* outrow = out + (size_t)row * D_;
#pragma unroll
            for (int g = 0; g < 4; g++) {
                int col = cCol * 256 + wn + g * 8 + qc * 2;
                int h = col >> 6;
                float a = attn_row[(size_t)h * L_] * rt;
                float2 bvv = *reinterpret_cast<const float2*>(bv + col);
                float2 rv  = *reinterpret_cast<const float2*>(encrow + col);
                float2 o;
                o.x = (acc[f][g][half * 2 + 0] + bvv.x) * a + rv.x;
                o.y = (acc[f][g][half * 2 + 1] + bvv.y) * a + rv.y;
                *reinterpret_cast<float2*>(outrow + col) = o;
            }
        }
    }
}

// ===========================================================================
// Kernel 5: row LayerNorm in place (shfl + single cross-warp reduce)
// ===========================================================================
__global__ void k_ln(float* __restrict__ out,
                     const float* __restrict__ gamma,
                     const float* __restrict__ beta)
{
    size_t row = blockIdx.x;
    float4* o4 = reinterpret_cast<float4*>(out + row * D_);
    int t = threadIdx.x;
    float4 v = o4[t];
    float s  = v.x + v.y + v.z + v.w;
    float ss = v.x * v.x + v.y * v.y + v.z * v.z + v.w * v.w;
#pragma unroll
    for (int off = 16; off; off >>= 1) {
        s  += __shfl_xor_sync(0xFFFFFFFFu, s, off);
        ss += __shfl_xor_sync(0xFFFFFFFFu, ss, off);
    }
    __shared__ float as_[8], ass_[8];
    if ((t & 31) == 0) { as_[t >> 5] = s; ass_[t >> 5] = ss; }
    __syncthreads();
    float S = 0.f, SS = 0.f;
#pragma unroll
    for (int i = 0; i < 8; i++) { S += as_[i]; SS += ass_[i]; }
    float mean = S * (1.0f / (float)D_);
    float var  = SS * (1.0f / (float)D_) - mean * mean;
    float inv  = rsqrtf(var + 1e-5f);
    const float4* g4 = reinterpret_cast<const float4*>(gamma);
    const float4* b4 = reinterpret_cast<const float4*>(beta);
    float4 g = g4[t], bb = b4[t];
    float4 r;
    r.x = (v.x - mean) * inv * g.x + bb.x;
    r.y = (v.y - mean) * inv * g.y + bb.y;
    r.z = (v.z - mean) * inv * g.z + bb.z;
    r.w = (v.w - mean) * inv * g.w + bb.w;
    o4[t] = r;
}

// ===========================================================================
extern "C" void kernel_launch(void* const* d_in, const int* in_sizes, int n_in,
                              void* d_out, int out_size) {
    const float* enc   = (const float*)d_in[0];
    const float* wq    = (const float*)d_in[1];
    const float* bq    = (const float*)d_in[2];
    const float* wk    = (const float*)d_in[3];
    const float* bk    = (const float*)d_in[4];
    const float* wv    = (const float*)d_in[5];
    const float* bv    = (const float*)d_in[6];
    const float* gamma = (const float*)d_in[7];
    const float* beta  = (const float*)d_in[8];
    float* out = (float*)d_out;

    cudaFuncSetAttribute(k_gemm_mma, cudaFuncAttributeMaxDynamicSharedMemorySize,
                         SMEM_GEMM);
    cudaFuncSetAttribute(k_scores, cudaFuncAttributeMaxDynamicSharedMemorySize,
                         SC_ROWS * D_ * 4);

    k_conv_wv<<<dim3(D_ / 32, D_ / 32), dim3(32, 8)>>>(wv);
    k_q<<<dim3(D_ / 256, B_), 256>>>(enc, wq, bq);
    k_u<<<dim3(8, H_), 128>>>(wk, bk);
    k_scores<<<dim3(L_ / SC_ROWS, B_), 256, SC_ROWS * D_ * 4>>>(enc);
    k_lsm<<<B_ * H_, 256>>>();
    k_gemm_mma<<<dim3(D_ / 256, M_ / 128), 512, SMEM_GEMM>>>(enc, bv, out);
    k_ln<<<M_, 256>>>(out, gamma, beta);
}